// round 1
// baseline (speedup 1.0000x reference)
#include <cuda_runtime.h>
#include <cstdint>
#include <cstddef>

#define D   64
#define H   4
#define HD  256
#define NEG 0.2f
#define BN_EPS 1e-5f

#define NMAX 50000
#define EMAX 800000

// ---------------- scratch (static device globals; no allocation) ----------------
__device__ float  g_h[(size_t)NMAX * HD];      // [N,256] GAT-transformed features
__device__ float  g_asrc[NMAX * H];
__device__ float  g_adst[NMAX * H];
__device__ int    g_cnt[NMAX];
__device__ int    g_rowptr[NMAX + 1];
__device__ int    g_cursor[NMAX];
__device__ int    g_csrc[EMAX];
__device__ int    g_bsum[256];
__device__ double g_sums[128];                 // [0:64) sum, [64:128) sumsq

// ============================================================================
// K1: fused  u = PReLU(x W_lin^T + b);  h = u W_gat^T;  a_src/a_dst head dots
// Block: 64 rows, 256 threads. Dynamic smem: xT[64][72] + uT[64][72] + W[64][264]
// ============================================================================
#define K1_SMEM ((2*64*72 + 64*264) * 4)

__global__ __launch_bounds__(256) void k_linear(
    const float* __restrict__ x, const float* __restrict__ Wlin,
    const float* __restrict__ blin, const float* __restrict__ pw,
    const float* __restrict__ Wgat, const float* __restrict__ attS,
    const float* __restrict__ attD, int nrows)
{
    extern __shared__ float sm[];
    float* sX = sm;                  // [64][72]  xT: sX[k*72 + r]
    float* sU = sm + 64 * 72;        // [64][72]  uT
    float* sW = sm + 2 * 64 * 72;    // [64][264] weight (transposed [k][out])
    const int tid  = threadIdx.x;
    const int row0 = blockIdx.x * 64;

    // load x tile transposed (coalesced read along k)
    for (int i = tid; i < 64 * 64; i += 256) {
        int r = i >> 6, k = i & 63;
        int gr = row0 + r;
        sX[k * 72 + r] = (gr < nrows) ? x[(size_t)gr * D + k] : 0.f;
    }
    // load W_lin transposed: Wlin[j][k] -> sW[k][j]
    for (int i = tid; i < 64 * 64; i += 256) {
        int j = i >> 6, k = i & 63;
        sW[k * 264 + j] = Wlin[i];
    }
    __syncthreads();

    // ---- stage A: y = x W_lin^T + b; PReLU; store transposed into sU ----
    {
        const int rg = (tid >> 4) << 2;   // row group (4 rows)
        const int cg = (tid & 15) << 2;   // col group (4 cols)
        float acc[4][4];
        #pragma unroll
        for (int a = 0; a < 4; a++)
            #pragma unroll
            for (int b = 0; b < 4; b++) acc[a][b] = 0.f;
        #pragma unroll 8
        for (int k = 0; k < 64; k++) {
            float4 a4 = *(const float4*)(sX + k * 72 + rg);
            float4 b4 = *(const float4*)(sW + k * 264 + cg);
            float av[4] = {a4.x, a4.y, a4.z, a4.w};
            float bv[4] = {b4.x, b4.y, b4.z, b4.w};
            #pragma unroll
            for (int ri = 0; ri < 4; ri++)
                #pragma unroll
                for (int cj = 0; cj < 4; cj++) acc[ri][cj] += av[ri] * bv[cj];
        }
        float4 bb = *(const float4*)(blin + cg);
        float4 pp = *(const float4*)(pw + cg);
        float bvb[4] = {bb.x, bb.y, bb.z, bb.w};
        float pvb[4] = {pp.x, pp.y, pp.z, pp.w};
        #pragma unroll
        for (int ri = 0; ri < 4; ri++)
            #pragma unroll
            for (int cj = 0; cj < 4; cj++) {
                float v = acc[ri][cj] + bvb[cj];
                v = (v >= 0.f) ? v : pvb[cj] * v;
                sU[(cg + cj) * 72 + rg + ri] = v;
            }
    }
    __syncthreads();
    // load W_gat transposed: Wgat[m][k] -> sW[k][m]
    for (int i = tid; i < 256 * 64; i += 256) {
        int m = i >> 6, k = i & 63;
        sW[k * 264 + m] = Wgat[i];
    }
    __syncthreads();

    // ---- stage B: h = u W_gat^T (8x8 micro-tiles), + attention dots ----
    const int lane = tid & 31;
    const int r0   = (tid >> 5) << 3;   // 8-row group
    const int mlo  = lane << 2;         // cols [mlo, mlo+4)
    const int mhi  = 128 + mlo;         // cols [mhi, mhi+4)  (conflict-free split)
    float acc[8][8];
    #pragma unroll
    for (int a = 0; a < 8; a++)
        #pragma unroll
        for (int b = 0; b < 8; b++) acc[a][b] = 0.f;

    #pragma unroll 8
    for (int k = 0; k < 64; k++) {
        float4 a0 = *(const float4*)(sU + k * 72 + r0);
        float4 a1 = *(const float4*)(sU + k * 72 + r0 + 4);
        float4 b0 = *(const float4*)(sW + k * 264 + mlo);
        float4 b1 = *(const float4*)(sW + k * 264 + mhi);
        float av[8] = {a0.x, a0.y, a0.z, a0.w, a1.x, a1.y, a1.z, a1.w};
        float bv[8] = {b0.x, b0.y, b0.z, b0.w, b1.x, b1.y, b1.z, b1.w};
        #pragma unroll
        for (int ri = 0; ri < 8; ri++)
            #pragma unroll
            for (int cj = 0; cj < 8; cj++) acc[ri][cj] += av[ri] * bv[cj];
    }

    const int hhA  = lane >> 4;      // head of mlo cols (0/1)
    const int hhB  = hhA + 2;        // head of mhi cols (2/3)
    const int dloc = mlo & 63;
    float4 sa0 = *(const float4*)(attS + hhA * 64 + dloc);
    float4 sa1 = *(const float4*)(attS + hhB * 64 + dloc);
    float4 da0 = *(const float4*)(attD + hhA * 64 + dloc);
    float4 da1 = *(const float4*)(attD + hhB * 64 + dloc);

    #pragma unroll
    for (int ri = 0; ri < 8; ri++) {
        int gr = row0 + r0 + ri;
        bool ok = gr < nrows;
        if (ok) {
            *(float4*)(g_h + (size_t)gr * HD + mlo) =
                make_float4(acc[ri][0], acc[ri][1], acc[ri][2], acc[ri][3]);
            *(float4*)(g_h + (size_t)gr * HD + mhi) =
                make_float4(acc[ri][4], acc[ri][5], acc[ri][6], acc[ri][7]);
        }
        float psA = acc[ri][0]*sa0.x + acc[ri][1]*sa0.y + acc[ri][2]*sa0.z + acc[ri][3]*sa0.w;
        float psB = acc[ri][4]*sa1.x + acc[ri][5]*sa1.y + acc[ri][6]*sa1.z + acc[ri][7]*sa1.w;
        float pdA = acc[ri][0]*da0.x + acc[ri][1]*da0.y + acc[ri][2]*da0.z + acc[ri][3]*da0.w;
        float pdB = acc[ri][4]*da1.x + acc[ri][5]*da1.y + acc[ri][6]*da1.z + acc[ri][7]*da1.w;
        #pragma unroll
        for (int off = 8; off; off >>= 1) {
            psA += __shfl_down_sync(0xffffffffu, psA, off, 16);
            psB += __shfl_down_sync(0xffffffffu, psB, off, 16);
            pdA += __shfl_down_sync(0xffffffffu, pdA, off, 16);
            pdB += __shfl_down_sync(0xffffffffu, pdB, off, 16);
        }
        if (((lane & 15) == 0) && ok) {
            g_asrc[gr * H + hhA] = psA;
            g_asrc[gr * H + hhB] = psB;
            g_adst[gr * H + hhA] = pdA;
            g_adst[gr * H + hhB] = pdB;
        }
    }
}

// ============================================================================
// CSR build: histogram -> 3-kernel exclusive scan -> scatter
// ============================================================================
__global__ void k_zero_cnt(int n) {
    int i = blockIdx.x * blockDim.x + threadIdx.x;
    if (i < n) g_cnt[i] = 0;
}

__global__ void k_hist(const int* __restrict__ dst, int e) {
    for (int i = blockIdx.x * blockDim.x + threadIdx.x; i < e;
         i += gridDim.x * blockDim.x)
        atomicAdd(&g_cnt[dst[i]], 1);
}

__global__ void k_scanA(int n) {
    __shared__ int sh[512];
    int i = blockIdx.x * 512 + threadIdx.x;
    int v = (i < n) ? g_cnt[i] : 0;
    sh[threadIdx.x] = v;
    __syncthreads();
    #pragma unroll
    for (int off = 1; off < 512; off <<= 1) {
        int t = (threadIdx.x >= off) ? sh[threadIdx.x - off] : 0;
        __syncthreads();
        sh[threadIdx.x] += t;
        __syncthreads();
    }
    if (i < n) g_rowptr[i] = sh[threadIdx.x] - v;   // exclusive
    if (threadIdx.x == 511) g_bsum[blockIdx.x] = sh[511];
}

__global__ void k_scanB(int nch) {
    if (threadIdx.x == 0) {
        int run = 0;
        for (int j = 0; j < nch; j++) { int t = g_bsum[j]; g_bsum[j] = run; run += t; }
    }
}

__global__ void k_scanC(int n, int e) {
    int i = blockIdx.x * blockDim.x + threadIdx.x;
    if (i < n) {
        int v = g_rowptr[i] + g_bsum[i >> 9];
        g_rowptr[i] = v;
        g_cursor[i] = v;
    }
    if (i == 0) g_rowptr[n] = e;
}

__global__ void k_scatter(const int* __restrict__ src, const int* __restrict__ dst, int e) {
    for (int i = blockIdx.x * blockDim.x + threadIdx.x; i < e;
         i += gridDim.x * blockDim.x) {
        int d = dst[i];
        int pos = atomicAdd(&g_cursor[d], 1);
        g_csrc[pos] = src[i];
    }
}

// ============================================================================
// K4: warp-per-node single-pass online-softmax aggregation (+ self loop,
//     + head mean folded). Writes pre-BN result into out [N,64].
// ============================================================================
__global__ __launch_bounds__(256) void k_gather(float* __restrict__ out, int nnodes)
{
    int gw = (blockIdx.x * blockDim.x + threadIdx.x) >> 5;
    if (gw >= nnodes) return;
    const int lane = threadIdx.x & 31;
    const int hp   = lane >> 4;          // head-pair: 0 -> heads{0,1}, 1 -> {2,3}
    const int dq   = (lane & 15) << 2;   // 4 consecutive d
    const int h0   = hp * 2, h1 = hp * 2 + 1;

    float adv = 0.f;
    if (lane < 4) adv = g_adst[gw * H + lane];

    // self loop (src = gw) initializes running max / denom / accumulators
    float el = 0.f;
    if (lane < 4) {
        float t = g_asrc[gw * H + lane] + adv;
        el = (t >= 0.f) ? t : NEG * t;
    }
    float m0 = __shfl_sync(0xffffffffu, el, h0);
    float m1 = __shfl_sync(0xffffffffu, el, h1);
    float s0 = 1.f, s1 = 1.f;
    const float4* hr = (const float4*)(g_h + (size_t)gw * HD);
    float4 A0 = hr[(h0 << 4) + (dq >> 2)];
    float4 A1 = hr[(h1 << 4) + (dq >> 2)];

    const int eb = g_rowptr[gw], ee = g_rowptr[gw + 1];
    for (int e = eb; e < ee; e++) {
        int s = g_csrc[e];
        float elv = 0.f;
        if (lane < 4) {
            float t = g_asrc[s * H + lane] + adv;
            elv = (t >= 0.f) ? t : NEG * t;
        }
        float e0 = __shfl_sync(0xffffffffu, elv, h0);
        float e1 = __shfl_sync(0xffffffffu, elv, h1);
        float w0, w1;
        if (e0 > m0) {
            float sc = __expf(m0 - e0);
            s0 *= sc; A0.x *= sc; A0.y *= sc; A0.z *= sc; A0.w *= sc;
            m0 = e0; w0 = 1.f;
        } else w0 = __expf(e0 - m0);
        if (e1 > m1) {
            float sc = __expf(m1 - e1);
            s1 *= sc; A1.x *= sc; A1.y *= sc; A1.z *= sc; A1.w *= sc;
            m1 = e1; w1 = 1.f;
        } else w1 = __expf(e1 - m1);
        s0 += w0; s1 += w1;
        const float4* hs = (const float4*)(g_h + (size_t)s * HD);
        float4 v0 = hs[(h0 << 4) + (dq >> 2)];
        float4 v1 = hs[(h1 << 4) + (dq >> 2)];
        A0.x += w0 * v0.x; A0.y += w0 * v0.y; A0.z += w0 * v0.z; A0.w += w0 * v0.w;
        A1.x += w1 * v1.x; A1.y += w1 * v1.y; A1.z += w1 * v1.z; A1.w += w1 * v1.w;
    }

    float i0 = 1.f / s0, i1 = 1.f / s1;
    float p0 = A0.x * i0 + A1.x * i1;
    float p1 = A0.y * i0 + A1.y * i1;
    float p2 = A0.z * i0 + A1.z * i1;
    float p3 = A0.w * i0 + A1.w * i1;
    p0 += __shfl_xor_sync(0xffffffffu, p0, 16);
    p1 += __shfl_xor_sync(0xffffffffu, p1, 16);
    p2 += __shfl_xor_sync(0xffffffffu, p2, 16);
    p3 += __shfl_xor_sync(0xffffffffu, p3, 16);
    if (hp == 0) {
        *(float4*)(out + (size_t)gw * D + dq) =
            make_float4(p0 * 0.25f, p1 * 0.25f, p2 * 0.25f, p3 * 0.25f);
    }
}

// ============================================================================
// BatchNorm (batch stats, gat_bias cancels) + ReLU
// ============================================================================
__global__ void k_zero_sums() {
    if (threadIdx.x < 128) g_sums[threadIdx.x] = 0.0;
}

__global__ void k_bnstats(const float* __restrict__ out, int nnodes) {
    __shared__ double shs[256], shq[256];
    const int c = threadIdx.x & 63;
    const int g = threadIdx.x >> 6;   // 0..3
    double s = 0.0, q = 0.0;
    for (int r = blockIdx.x * 4 + g; r < nnodes; r += gridDim.x * 4) {
        float v = out[(size_t)r * D + c];
        s += v;
        q += (double)v * v;
    }
    shs[threadIdx.x] = s; shq[threadIdx.x] = q;
    __syncthreads();
    if (g == 0) {
        s = shs[c] + shs[c + 64] + shs[c + 128] + shs[c + 192];
        q = shq[c] + shq[c + 64] + shq[c + 128] + shq[c + 192];
        atomicAdd(&g_sums[c], s);
        atomicAdd(&g_sums[64 + c], q);
    }
}

__global__ void k_bnfinal(float* __restrict__ out, const float* __restrict__ gamma,
                          const float* __restrict__ beta, int nnodes) {
    int i = blockIdx.x * blockDim.x + threadIdx.x;
    int total = nnodes * 16;
    if (i >= total) return;
    int c4 = (i & 15) << 2;
    float4 v = ((float4*)out)[i];
    float r[4] = {v.x, v.y, v.z, v.w};
    #pragma unroll
    for (int j = 0; j < 4; j++) {
        int c = c4 + j;
        double mean = g_sums[c] / nnodes;
        double var  = g_sums[64 + c] / nnodes - mean * mean;
        float scale = gamma[c] * rsqrtf((float)var + BN_EPS);
        float shf   = beta[c] - (float)mean * scale;
        r[j] = fmaxf(0.f, r[j] * scale + shf);
    }
    ((float4*)out)[i] = make_float4(r[0], r[1], r[2], r[3]);
}

// ============================================================================
extern "C" void kernel_launch(void* const* d_in, const int* in_sizes, int n_in,
                              void* d_out, int out_size)
{
    const float* x    = (const float*)d_in[0];
    const int*   ei   = (const int*)  d_in[1];
    const float* Wlin = (const float*)d_in[2];
    const float* blin = (const float*)d_in[3];
    const float* pw   = (const float*)d_in[4];
    const float* Wgat = (const float*)d_in[5];
    const float* attS = (const float*)d_in[6];
    const float* attD = (const float*)d_in[7];
    // d_in[8] = gat_bias: cancels under batch-stat BatchNorm, unused.
    const float* gamma = (const float*)d_in[9];
    const float* beta  = (const float*)d_in[10];
    float* out = (float*)d_out;

    int n = in_sizes[0] / D;     // 50000
    int e = in_sizes[1] / 2;     // 800000
    const int* srcA = ei;
    const int* dstA = ei + e;

    cudaFuncSetAttribute(k_linear, cudaFuncAttributeMaxDynamicSharedMemorySize, K1_SMEM);

    k_linear<<<(n + 63) / 64, 256, K1_SMEM>>>(x, Wlin, blin, pw, Wgat, attS, attD, n);

    k_zero_cnt<<<(n + 255) / 256, 256>>>(n);
    k_hist<<<1024, 256>>>(dstA, e);
    int nch = (n + 511) / 512;
    k_scanA<<<nch, 512>>>(n);
    k_scanB<<<1, 32>>>(nch);
    k_scanC<<<(n + 255) / 256, 256>>>(n, e);
    k_scatter<<<1024, 256>>>(srcA, dstA, e);

    k_gather<<<(n * 32 + 255) / 256, 256>>>(out, n);

    k_zero_sums<<<1, 128>>>();
    k_bnstats<<<200, 256>>>(out, n);
    k_bnfinal<<<(n * 16 + 255) / 256, 256>>>(out, gamma, beta, n);
}